// round 10
// baseline (speedup 1.0000x reference)
#include <cuda_runtime.h>
#include <cuda_fp16.h>
#include <cstdint>

// ---------------------------------------------------------------------------
// FermiLayer: N=512 (256 up / 256 dn), SINGLE=256, PAIR=128
// inputs: [0] h_one (512,256) [1] h_two (512,512,128) [2] W1 (512,256)
//         [3] b1 (256) [4] Wg (512,256) [5] W2 (128,128) [6] b2 (128)
// output: [h_one_out | h_two_out] fp32
// k_two: single-pass fp16 mma.sync (A and W both rounded once), 128x128
// tiles, 3 CTAs/SM. g2 partials fused into k_two; gtp blocks ride on its
// grid. Total rel err budget ~3e-4 (threshold 1e-3).
// ---------------------------------------------------------------------------

#define GAIN    1.5927812698663017f
#define RSQRT2  0.7071067811865475f
#define INV256  0.00390625f

typedef unsigned long long u64;
typedef unsigned int u32;

// scratch (__device__ globals: allocation-free rule)
__device__ float g_g2p[4 * 512 * 128];   // [(s*2+h)][j][p] partial sums (128 i each)
__device__ float g_g1p[16 * 256];        // g1 partials: [s*8+ck][c], 32 rows each
__device__ float g_gtp[16 * 256];        // gt partials (16 k-chunks)
// W2^T fp16 in padded [n][k] layout (row stride 272B)
__device__ __align__(16) unsigned char g_w2h[35840];

__device__ __forceinline__ float tanh_fast(float x) {
    float y;
    asm("tanh.approx.f32 %0, %1;" : "=f"(y) : "f"(x));
    return y;
}
__device__ __forceinline__ u32 smem_u32(const void* p) {
    u32 a;
    asm("{ .reg .u64 t; cvta.to.shared.u64 t, %1; cvt.u32.u64 %0, t; }" : "=r"(a) : "l"(p));
    return a;
}
__device__ __forceinline__ void ldsm4(u32* r, u32 addr) {
    asm volatile("ldmatrix.sync.aligned.m8n8.x4.shared.b16 {%0,%1,%2,%3}, [%4];"
                 : "=r"(r[0]), "=r"(r[1]), "=r"(r[2]), "=r"(r[3]) : "r"(addr));
}
__device__ __forceinline__ void mma16816(float* c, const u32* a, const u32* b) {
    asm volatile(
        "mma.sync.aligned.m16n8k16.row.col.f32.f16.f16.f32 "
        "{%0,%1,%2,%3}, {%4,%5,%6,%7}, {%8,%9}, {%0,%1,%2,%3};"
        : "+f"(c[0]), "+f"(c[1]), "+f"(c[2]), "+f"(c[3])
        : "r"(a[0]), "r"(a[1]), "r"(a[2]), "r"(a[3]), "r"(b[0]), "r"(b[1]));
}

// ---------------------------------------------------------------------------
// K0: merged prep. blocks 0..15: W2T fp16 image. blocks 16..31: g1 partials.
// ---------------------------------------------------------------------------
#define BSTRIDE 272

__global__ void k_prep(const float* __restrict__ W2,
                       const float* __restrict__ h_one) {
    int b = blockIdx.x;
    if (b < 16) {
        int t = b * 256 + threadIdx.x;   // 0..4095
        int n = t >> 5;
        int k = (t & 31) * 4;
        __half2 h0 = __float22half2_rn(make_float2(W2[(k + 0) * 128 + n], W2[(k + 1) * 128 + n]));
        __half2 h1 = __float22half2_rn(make_float2(W2[(k + 2) * 128 + n], W2[(k + 3) * 128 + n]));
        u64 hp = (u64)(*(u32*)&h0) | ((u64)(*(u32*)&h1) << 32);
        *(u64*)(g_w2h + n * BSTRIDE + k * 2) = hp;
    } else {
        int bb = b - 16;
        int s = bb >> 3, ck = bb & 7;
        int c = threadIdx.x;
        const float* p = h_one + (size_t)(s * 256 + ck * 32) * 256 + c;
        float sum = 0.f;
#pragma unroll 8
        for (int r = 0; r < 32; r++) sum += p[r * 256];
        g_g1p[bb * 256 + c] = sum;
    }
}

// ---------------------------------------------------------------------------
// K2: h_one path. 128 blocks x 256 threads, 4 rows/block.
// Folds g2 partial combine (2 halves/spin) and gt combine (+b1).
// ---------------------------------------------------------------------------
__global__ void __launch_bounds__(256)
k_one(const float* __restrict__ h_one,
      const float* __restrict__ W1,
      const float* __restrict__ b1,
      float* __restrict__ out_one) {
    __shared__ float s_in[2048];   // [k][r], k=0..511, r=0..3
    int tid = threadIdx.x;
    int r0 = blockIdx.x * 4;
#pragma unroll
    for (int i = 0; i < 8; i++) {
        int e = tid + i * 256;     // 0..2047
        int k = e >> 2;
        int r = e & 3;
        int n = r0 + r;
        float v;
        if (k < 256) {
            v = h_one[n * 256 + k];
        } else {
            int sp = (k < 384) ? 0 : 1;
            int p = k - 256 - sp * 128;
            size_t base = (size_t)(sp * 2) * 65536 + (size_t)n * 128 + p;
            v = (g_g2p[base] + g_g2p[base + 65536]) * INV256;
        }
        s_in[k * 4 + r] = v;
    }
    __syncthreads();

    int c = tid;
    float acc[4] = {0.f, 0.f, 0.f, 0.f};
#pragma unroll 4
    for (int kb = 0; kb < 64; kb++) {
        float w[8];
#pragma unroll
        for (int i = 0; i < 8; i++) w[i] = W1[(kb * 8 + i) * 256 + c];
#pragma unroll
        for (int i = 0; i < 8; i++) {
            float4 a = *(const float4*)(s_in + (kb * 8 + i) * 4);
            acc[0] += a.x * w[i];
            acc[1] += a.y * w[i];
            acc[2] += a.z * w[i];
            acc[3] += a.w * w[i];
        }
    }
    float gt = b1[c];
#pragma unroll
    for (int q = 0; q < 16; q++) gt += g_gtp[q * 256 + c];
#pragma unroll
    for (int r = 0; r < 4; r++) {
        float pre = (acc[r] + gt) * RSQRT2;
        out_one[(r0 + r) * 256 + c] = (s_in[c * 4 + r] + GAIN * tanh_fast(pre)) * RSQRT2;
    }
}

// ---------------------------------------------------------------------------
// K3: single-pass fp16 mma.sync h_two kernel + fused g2 partials + gtp.
// grid 2064: blocks < 2048 do GEMM tiles; blocks 2048..2063 do gt partials.
// GEMM: bid -> j = bid&511, ch = bid>>9 (0..3): s = ch>>1, h = ch&1.
// Tile = 128 senders x 128 cols, fixed receiver j. Warp = 32m x 64n.
// ---------------------------------------------------------------------------
#define S_AH  0
#define S_WH  34816
#define S_RED 69632
#define SMEM_TWO 73728

__global__ void __launch_bounds__(256, 3)
k_two(const float* __restrict__ h_two,
      const float* __restrict__ b2,
      const float* __restrict__ Wg,
      float* __restrict__ out_two) {
    extern __shared__ char smem[];
    int tid = threadIdx.x;

    if (blockIdx.x >= 2048) {
        // ---- gt partials: block q covers k in [q*32, q*32+32) ----
        __shared__ float s_g1[32];
        int q = blockIdx.x - 2048;
        int c = tid;
        if (c < 32) {
            int kk = q * 32 + c;
            int s = kk >> 8;
            int col = kk & 255;
            float sum = 0.f;
#pragma unroll
            for (int ck = 0; ck < 8; ck++) sum += g_g1p[(s * 8 + ck) * 256 + col];
            s_g1[c] = sum * INV256;
        }
        __syncthreads();
        float acc = 0.f;
#pragma unroll
        for (int kb = 0; kb < 4; kb++) {
            float w[8];
#pragma unroll
            for (int i = 0; i < 8; i++) w[i] = Wg[(q * 32 + kb * 8 + i) * 256 + c];
#pragma unroll
            for (int i = 0; i < 8; i++) acc += s_g1[kb * 8 + i] * w[i];
        }
        g_gtp[q * 256 + c] = acc;
        return;
    }

    u32 sb = smem_u32(smem);
    int lane = tid & 31;
    int w = tid >> 5;

    int j = blockIdx.x & 511;
    int ch = blockIdx.x >> 9;      // 0..3
    int s = ch >> 1;
    int h = ch & 1;
    int ibase = s * 256 + h * 128;

    // stage W2T fp16 image: 2176 uint4
    {
        const uint4* wh = (const uint4*)g_w2h;
        uint4* dh = (uint4*)(smem + S_WH);
        for (int idx = tid; idx < 2176; idx += 256) dh[idx] = wh[idx];
    }
    // stage A tile (128 rows): round fp32 -> fp16 + column sums
    {
        int rr = tid >> 5;          // 0..7
        int kc = tid & 31;          // k-quad
        const float* base = h_two + (size_t)(ibase + rr) * 65536 + (size_t)j * 128 + kc * 4;
        float4 csum = make_float4(0.f, 0.f, 0.f, 0.f);
#pragma unroll
        for (int it = 0; it < 16; it++) {
            int row = rr + it * 8;
            float4 v = *(const float4*)(base + (size_t)it * 8 * 65536);
            csum.x += v.x; csum.y += v.y; csum.z += v.z; csum.w += v.w;
            __half2 h0 = __float22half2_rn(make_float2(v.x, v.y));
            __half2 h1 = __float22half2_rn(make_float2(v.z, v.w));
            u64 hp = (u64)(*(u32*)&h0) | ((u64)(*(u32*)&h1) << 32);
            *(u64*)(smem + S_AH + row * BSTRIDE + kc * 8) = hp;
        }
        *(float4*)(smem + S_RED + (rr * 32 + kc) * 16) = csum;
    }
    __syncthreads();

    // g2 partial: threads 0..127 reduce 8 rr-partials for column p=tid
    if (tid < 128) {
        int p = tid;
        float sum = 0.f;
#pragma unroll
        for (int rr = 0; rr < 8; rr++)
            sum += *(const float*)(smem + S_RED + (rr * 32 + (p >> 2)) * 16 + (p & 3) * 4);
        g_g2p[(size_t)(s * 2 + h) * 65536 + (size_t)j * 128 + p] = sum;
    }

    int mw = w & 3;       // m-block: rows mw*32
    int nw = w >> 2;      // n-block: cols nw*64

    u32 a_off = (u32)((mw * 32 + (lane & 15)) * BSTRIDE + ((lane >> 4) << 4));
    u32 b_off = (u32)((((lane & 7) + ((lane >> 4) << 3)) * BSTRIDE) + (((lane >> 3) & 1) << 4));
    u32 Ah = sb + S_AH + a_off;
    u32 Bb = sb + S_WH + (u32)(nw * 64 * BSTRIDE) + b_off;

    float acc[2][8][4];
#pragma unroll
    for (int mi = 0; mi < 2; mi++)
#pragma unroll
        for (int nt = 0; nt < 8; nt++)
#pragma unroll
            for (int c = 0; c < 4; c++) acc[mi][nt][c] = 0.f;

#pragma unroll
    for (int ks = 0; ks < 8; ks++) {
        u32 b[4][4], a0[4], a1[4];
#pragma unroll
        for (int nb = 0; nb < 4; nb++) ldsm4(b[nb], Bb + nb * 16 * BSTRIDE + ks * 32);
        ldsm4(a0, Ah + ks * 32);
        ldsm4(a1, Ah + 16 * BSTRIDE + ks * 32);
#pragma unroll
        for (int nb = 0; nb < 4; nb++) {
            mma16816(acc[0][nb * 2 + 0], a0, b[nb]);
            mma16816(acc[0][nb * 2 + 1], a0, b[nb] + 2);
            mma16816(acc[1][nb * 2 + 0], a1, b[nb]);
            mma16816(acc[1][nb * 2 + 1], a1, b[nb] + 2);
        }
    }

    // epilogue: out = (Ah + GAIN*tanh(D + b2)) * RSQRT2
    int col0 = nw * 64 + (lane & 3) * 2;
    float2 bz[8];
#pragma unroll
    for (int nt = 0; nt < 8; nt++) bz[nt] = *(const float2*)(b2 + col0 + nt * 8);

#pragma unroll
    for (int mi = 0; mi < 2; mi++) {
#pragma unroll
        for (int half = 0; half < 2; half++) {
            int rt = mw * 32 + mi * 16 + half * 8 + (lane >> 2);
            float* orow = out_two + ((size_t)(ibase + rt) * 512 + j) * 128;
#pragma unroll
            for (int nt = 0; nt < 8; nt++) {
                int c = col0 + nt * 8;
                __half2 hh = *(const __half2*)(smem + S_AH + rt * BSTRIDE + c * 2);
                float2 hf = __half22float2(hh);
                float d0 = acc[mi][nt][half * 2 + 0] + bz[nt].x;
                float d1 = acc[mi][nt][half * 2 + 1] + bz[nt].y;
                float2 o;
                o.x = (hf.x + GAIN * tanh_fast(d0)) * RSQRT2;
                o.y = (hf.y + GAIN * tanh_fast(d1)) * RSQRT2;
                *(float2*)(orow + c) = o;
            }
        }
    }
}

// ---------------------------------------------------------------------------
extern "C" void kernel_launch(void* const* d_in, const int* in_sizes, int n_in,
                              void* d_out, int out_size) {
    const float* h_one = (const float*)d_in[0];
    const float* h_two = (const float*)d_in[1];
    const float* W1    = (const float*)d_in[2];
    const float* b1    = (const float*)d_in[3];
    const float* Wg    = (const float*)d_in[4];
    const float* W2    = (const float*)d_in[5];
    const float* b2    = (const float*)d_in[6];

    float* out_one = (float*)d_out;
    float* out_two = (float*)d_out + 512 * 256;

    cudaFuncSetAttribute(k_two, cudaFuncAttributeMaxDynamicSharedMemorySize, SMEM_TWO);

    k_prep<<<32, 256>>>(W2, h_one);
    k_two<<<2064, 256, SMEM_TWO>>>(h_two, b2, Wg, out_two);
    k_one<<<128, 256>>>(h_one, W1, b1, out_one);
}

// round 11
// speedup vs baseline: 1.8184x; 1.8184x over previous
#include <cuda_runtime.h>
#include <cuda_fp16.h>
#include <cstdint>

// ---------------------------------------------------------------------------
// FermiLayer: N=512 (256 up / 256 dn), SINGLE=256, PAIR=128
// inputs: [0] h_one (512,256) [1] h_two (512,512,128) [2] W1 (512,256)
//         [3] b1 (256) [4] Wg (512,256) [5] W2 (128,128) [6] b2 (128)
// output: [h_one_out | h_two_out] fp32
// k_two: single-pass fp16 mma.sync (A and W rounded once), 128x128 tiles,
// 2 CTAs/SM (124 regs, NO spills -- launch_bounds(256,3) caused the round-10
// regression via forced register cap). g2 partials + gtp fused into k_two.
// ---------------------------------------------------------------------------

#define GAIN    1.5927812698663017f
#define RSQRT2  0.7071067811865475f
#define INV256  0.00390625f

typedef unsigned long long u64;
typedef unsigned int u32;

// scratch (__device__ globals: allocation-free rule)
__device__ float g_g2p[4 * 512 * 128];   // [(s*2+h)][j][p] partial sums (128 i each)
__device__ float g_g1p[16 * 256];        // g1 partials: [s*8+ck][c], 32 rows each
__device__ float g_gtp[16 * 256];        // gt partials (16 k-chunks)
// W2^T fp16 in padded [n][k] layout (row stride 272B)
__device__ __align__(16) unsigned char g_w2h[35840];

__device__ __forceinline__ float tanh_fast(float x) {
    float y;
    asm("tanh.approx.f32 %0, %1;" : "=f"(y) : "f"(x));
    return y;
}
__device__ __forceinline__ u32 smem_u32(const void* p) {
    u32 a;
    asm("{ .reg .u64 t; cvta.to.shared.u64 t, %1; cvt.u32.u64 %0, t; }" : "=r"(a) : "l"(p));
    return a;
}
__device__ __forceinline__ void ldsm4(u32* r, u32 addr) {
    asm volatile("ldmatrix.sync.aligned.m8n8.x4.shared.b16 {%0,%1,%2,%3}, [%4];"
                 : "=r"(r[0]), "=r"(r[1]), "=r"(r[2]), "=r"(r[3]) : "r"(addr));
}
__device__ __forceinline__ void mma16816(float* c, const u32* a, const u32* b) {
    asm volatile(
        "mma.sync.aligned.m16n8k16.row.col.f32.f16.f16.f32 "
        "{%0,%1,%2,%3}, {%4,%5,%6,%7}, {%8,%9}, {%0,%1,%2,%3};"
        : "+f"(c[0]), "+f"(c[1]), "+f"(c[2]), "+f"(c[3])
        : "r"(a[0]), "r"(a[1]), "r"(a[2]), "r"(a[3]), "r"(b[0]), "r"(b[1]));
}

// ---------------------------------------------------------------------------
// K0: merged prep. blocks 0..15: W2T fp16 image. blocks 16..31: g1 partials.
// ---------------------------------------------------------------------------
#define BSTRIDE 272

__global__ void k_prep(const float* __restrict__ W2,
                       const float* __restrict__ h_one) {
    int b = blockIdx.x;
    if (b < 16) {
        int t = b * 256 + threadIdx.x;   // 0..4095
        int n = t >> 5;
        int k = (t & 31) * 4;
        __half2 h0 = __float22half2_rn(make_float2(W2[(k + 0) * 128 + n], W2[(k + 1) * 128 + n]));
        __half2 h1 = __float22half2_rn(make_float2(W2[(k + 2) * 128 + n], W2[(k + 3) * 128 + n]));
        u64 hp = (u64)(*(u32*)&h0) | ((u64)(*(u32*)&h1) << 32);
        *(u64*)(g_w2h + n * BSTRIDE + k * 2) = hp;
    } else {
        int bb = b - 16;
        int s = bb >> 3, ck = bb & 7;
        int c = threadIdx.x;
        const float* p = h_one + (size_t)(s * 256 + ck * 32) * 256 + c;
        float sum = 0.f;
#pragma unroll 8
        for (int r = 0; r < 32; r++) sum += p[r * 256];
        g_g1p[bb * 256 + c] = sum;
    }
}

// ---------------------------------------------------------------------------
// K2: h_one path. 128 blocks x 256 threads, 4 rows/block.
// Folds g2 partial combine (2 halves/spin) and gt combine (+b1).
// ---------------------------------------------------------------------------
__global__ void __launch_bounds__(256)
k_one(const float* __restrict__ h_one,
      const float* __restrict__ W1,
      const float* __restrict__ b1,
      float* __restrict__ out_one) {
    __shared__ float s_in[2048];   // [k][r], k=0..511, r=0..3
    int tid = threadIdx.x;
    int r0 = blockIdx.x * 4;
#pragma unroll
    for (int i = 0; i < 8; i++) {
        int e = tid + i * 256;     // 0..2047
        int k = e >> 2;
        int r = e & 3;
        int n = r0 + r;
        float v;
        if (k < 256) {
            v = h_one[n * 256 + k];
        } else {
            int sp = (k < 384) ? 0 : 1;
            int p = k - 256 - sp * 128;
            size_t base = (size_t)(sp * 2) * 65536 + (size_t)n * 128 + p;
            v = (g_g2p[base] + g_g2p[base + 65536]) * INV256;
        }
        s_in[k * 4 + r] = v;
    }
    __syncthreads();

    int c = tid;
    float acc[4] = {0.f, 0.f, 0.f, 0.f};
#pragma unroll 4
    for (int kb = 0; kb < 64; kb++) {
        float w[8];
#pragma unroll
        for (int i = 0; i < 8; i++) w[i] = W1[(kb * 8 + i) * 256 + c];
#pragma unroll
        for (int i = 0; i < 8; i++) {
            float4 a = *(const float4*)(s_in + (kb * 8 + i) * 4);
            acc[0] += a.x * w[i];
            acc[1] += a.y * w[i];
            acc[2] += a.z * w[i];
            acc[3] += a.w * w[i];
        }
    }
    float gt = b1[c];
#pragma unroll
    for (int q = 0; q < 16; q++) gt += g_gtp[q * 256 + c];
#pragma unroll
    for (int r = 0; r < 4; r++) {
        float pre = (acc[r] + gt) * RSQRT2;
        out_one[(r0 + r) * 256 + c] = (s_in[c * 4 + r] + GAIN * tanh_fast(pre)) * RSQRT2;
    }
}

// ---------------------------------------------------------------------------
// K3: single-pass fp16 mma.sync h_two kernel + fused g2 partials + gtp.
// grid 2064: blocks < 2048 do GEMM tiles; blocks 2048..2063 do gt partials.
// GEMM: bid -> j = bid&511, ch = bid>>9 (0..3): s = ch>>1, h = ch&1.
// Tile = 128 senders x 128 cols, fixed receiver j. Warp = 32m x 64n.
// ---------------------------------------------------------------------------
#define S_AH  0
#define S_WH  34816
#define S_RED 69632
#define SMEM_TWO 73728

__global__ void __launch_bounds__(256, 2)
k_two(const float* __restrict__ h_two,
      const float* __restrict__ b2,
      const float* __restrict__ Wg,
      float* __restrict__ out_two) {
    extern __shared__ char smem[];
    int tid = threadIdx.x;

    if (blockIdx.x >= 2048) {
        // ---- gt partials: block q covers k in [q*32, q*32+32) ----
        __shared__ float s_g1[32];
        int q = blockIdx.x - 2048;
        int c = tid;
        if (c < 32) {
            int kk = q * 32 + c;
            int s = kk >> 8;
            int col = kk & 255;
            float sum = 0.f;
#pragma unroll
            for (int ck = 0; ck < 8; ck++) sum += g_g1p[(s * 8 + ck) * 256 + col];
            s_g1[c] = sum * INV256;
        }
        __syncthreads();
        float acc = 0.f;
#pragma unroll
        for (int kb = 0; kb < 4; kb++) {
            float w[8];
#pragma unroll
            for (int i = 0; i < 8; i++) w[i] = Wg[(q * 32 + kb * 8 + i) * 256 + c];
#pragma unroll
            for (int i = 0; i < 8; i++) acc += s_g1[kb * 8 + i] * w[i];
        }
        g_gtp[q * 256 + c] = acc;
        return;
    }

    u32 sb = smem_u32(smem);
    int lane = tid & 31;
    int w = tid >> 5;

    int j = blockIdx.x & 511;
    int ch = blockIdx.x >> 9;      // 0..3
    int s = ch >> 1;
    int h = ch & 1;
    int ibase = s * 256 + h * 128;

    // stage W2T fp16 image: 2176 uint4
    {
        const uint4* wh = (const uint4*)g_w2h;
        uint4* dh = (uint4*)(smem + S_WH);
        for (int idx = tid; idx < 2176; idx += 256) dh[idx] = wh[idx];
    }
    // stage A tile (128 rows): round fp32 -> fp16 + column sums
    {
        int rr = tid >> 5;          // 0..7
        int kc = tid & 31;          // k-quad
        const float* base = h_two + (size_t)(ibase + rr) * 65536 + (size_t)j * 128 + kc * 4;
        float4 csum = make_float4(0.f, 0.f, 0.f, 0.f);
#pragma unroll
        for (int it = 0; it < 16; it++) {
            int row = rr + it * 8;
            float4 v = *(const float4*)(base + (size_t)it * 8 * 65536);
            csum.x += v.x; csum.y += v.y; csum.z += v.z; csum.w += v.w;
            __half2 h0 = __float22half2_rn(make_float2(v.x, v.y));
            __half2 h1 = __float22half2_rn(make_float2(v.z, v.w));
            u64 hp = (u64)(*(u32*)&h0) | ((u64)(*(u32*)&h1) << 32);
            *(u64*)(smem + S_AH + row * BSTRIDE + kc * 8) = hp;
        }
        *(float4*)(smem + S_RED + (rr * 32 + kc) * 16) = csum;
    }
    __syncthreads();

    // g2 partial: threads 0..127 reduce 8 rr-partials for column p=tid
    if (tid < 128) {
        int p = tid;
        float sum = 0.f;
#pragma unroll
        for (int rr = 0; rr < 8; rr++)
            sum += *(const float*)(smem + S_RED + (rr * 32 + (p >> 2)) * 16 + (p & 3) * 4);
        g_g2p[(size_t)(s * 2 + h) * 65536 + (size_t)j * 128 + p] = sum;
    }

    int mw = w & 3;       // m-block: rows mw*32
    int nw = w >> 2;      // n-block: cols nw*64

    u32 a_off = (u32)((mw * 32 + (lane & 15)) * BSTRIDE + ((lane >> 4) << 4));
    u32 b_off = (u32)((((lane & 7) + ((lane >> 4) << 3)) * BSTRIDE) + (((lane >> 3) & 1) << 4));
    u32 Ah = sb + S_AH + a_off;
    u32 Bb = sb + S_WH + (u32)(nw * 64 * BSTRIDE) + b_off;

    float acc[2][8][4];
#pragma unroll
    for (int mi = 0; mi < 2; mi++)
#pragma unroll
        for (int nt = 0; nt < 8; nt++)
#pragma unroll
            for (int c = 0; c < 4; c++) acc[mi][nt][c] = 0.f;

#pragma unroll
    for (int ks = 0; ks < 8; ks++) {
        u32 b[4][4], a0[4], a1[4];
#pragma unroll
        for (int nb = 0; nb < 4; nb++) ldsm4(b[nb], Bb + nb * 16 * BSTRIDE + ks * 32);
        ldsm4(a0, Ah + ks * 32);
        ldsm4(a1, Ah + 16 * BSTRIDE + ks * 32);
#pragma unroll
        for (int nb = 0; nb < 4; nb++) {
            mma16816(acc[0][nb * 2 + 0], a0, b[nb]);
            mma16816(acc[0][nb * 2 + 1], a0, b[nb] + 2);
            mma16816(acc[1][nb * 2 + 0], a1, b[nb]);
            mma16816(acc[1][nb * 2 + 1], a1, b[nb] + 2);
        }
    }

    // epilogue: out = (Ah + GAIN*tanh(D + b2)) * RSQRT2
    int col0 = nw * 64 + (lane & 3) * 2;
    float2 bz[8];
#pragma unroll
    for (int nt = 0; nt < 8; nt++) bz[nt] = *(const float2*)(b2 + col0 + nt * 8);

#pragma unroll
    for (int mi = 0; mi < 2; mi++) {
#pragma unroll
        for (int half = 0; half < 2; half++) {
            int rt = mw * 32 + mi * 16 + half * 8 + (lane >> 2);
            float* orow = out_two + ((size_t)(ibase + rt) * 512 + j) * 128;
#pragma unroll
            for (int nt = 0; nt < 8; nt++) {
                int c = col0 + nt * 8;
                __half2 hh = *(const __half2*)(smem + S_AH + rt * BSTRIDE + c * 2);
                float2 hf = __half22float2(hh);
                float d0 = acc[mi][nt][half * 2 + 0] + bz[nt].x;
                float d1 = acc[mi][nt][half * 2 + 1] + bz[nt].y;
                float2 o;
                o.x = (hf.x + GAIN * tanh_fast(d0)) * RSQRT2;
                o.y = (hf.y + GAIN * tanh_fast(d1)) * RSQRT2;
                *(float2*)(orow + c) = o;
            }
        }
    }
}

// ---------------------------------------------------------------------------
extern "C" void kernel_launch(void* const* d_in, const int* in_sizes, int n_in,
                              void* d_out, int out_size) {
    const float* h_one = (const float*)d_in[0];
    const float* h_two = (const float*)d_in[1];
    const float* W1    = (const float*)d_in[2];
    const float* b1    = (const float*)d_in[3];
    const float* Wg    = (const float*)d_in[4];
    const float* W2    = (const float*)d_in[5];
    const float* b2    = (const float*)d_in[6];

    float* out_one = (float*)d_out;
    float* out_two = (float*)d_out + 512 * 256;

    cudaFuncSetAttribute(k_two, cudaFuncAttributeMaxDynamicSharedMemorySize, SMEM_TWO);

    k_prep<<<32, 256>>>(W2, h_one);
    k_two<<<2064, 256, SMEM_TWO>>>(h_two, b2, Wg, out_two);
    k_one<<<128, 256>>>(h_one, W1, b1, out_one);
}

// round 12
// speedup vs baseline: 1.8554x; 1.0203x over previous
#include <cuda_runtime.h>
#include <cuda_fp16.h>
#include <cstdint>

// ---------------------------------------------------------------------------
// FermiLayer: N=512 (256 up / 256 dn), SINGLE=256, PAIR=128
// inputs: [0] h_one (512,256) [1] h_two (512,512,128) [2] W1 (512,256)
//         [3] b1 (256) [4] Wg (512,256) [5] W2 (128,128) [6] b2 (128)
// output: [h_one_out | h_two_out] fp32
// k_two: single-pass fp16 mma.sync, 128x128 tiles, 2 CTAs/SM, each block
// handles a j-PAIR with L2 prefetch of tile 2 issued during tile 1
// (register-free latency hiding). g2 partials + gtp fused into k_two.
// ---------------------------------------------------------------------------

#define GAIN    1.5927812698663017f
#define RSQRT2  0.7071067811865475f
#define INV256  0.00390625f

typedef unsigned long long u64;
typedef unsigned int u32;

// scratch (__device__ globals: allocation-free rule)
__device__ float g_g2p[4 * 512 * 128];   // [(s*2+h)][j][p] partial sums (128 i each)
__device__ float g_g1p[16 * 256];        // g1 partials
__device__ float g_gtp[16 * 256];        // gt partials (16 k-chunks)
__device__ __align__(16) unsigned char g_w2h[35840];  // W2^T fp16, stride 272B

__device__ __forceinline__ float tanh_fast(float x) {
    float y;
    asm("tanh.approx.f32 %0, %1;" : "=f"(y) : "f"(x));
    return y;
}
__device__ __forceinline__ u32 smem_u32(const void* p) {
    u32 a;
    asm("{ .reg .u64 t; cvta.to.shared.u64 t, %1; cvt.u32.u64 %0, t; }" : "=r"(a) : "l"(p));
    return a;
}
__device__ __forceinline__ void ldsm4(u32* r, u32 addr) {
    asm volatile("ldmatrix.sync.aligned.m8n8.x4.shared.b16 {%0,%1,%2,%3}, [%4];"
                 : "=r"(r[0]), "=r"(r[1]), "=r"(r[2]), "=r"(r[3]) : "r"(addr));
}
__device__ __forceinline__ void mma16816(float* c, const u32* a, const u32* b) {
    asm volatile(
        "mma.sync.aligned.m16n8k16.row.col.f32.f16.f16.f32 "
        "{%0,%1,%2,%3}, {%4,%5,%6,%7}, {%8,%9}, {%0,%1,%2,%3};"
        : "+f"(c[0]), "+f"(c[1]), "+f"(c[2]), "+f"(c[3])
        : "r"(a[0]), "r"(a[1]), "r"(a[2]), "r"(a[3]), "r"(b[0]), "r"(b[1]));
}
__device__ __forceinline__ void prefetch_l2(const void* p) {
    asm volatile("prefetch.global.L2 [%0];" :: "l"(p));
}

#define BSTRIDE 272
#define S_AH  0
#define S_WH  34816
#define S_RED 69632
#define SMEM_TWO 73728

// ---------------------------------------------------------------------------
// K0: merged prep. blocks 0..15: W2T fp16 image. blocks 16..31: g1 partials.
// ---------------------------------------------------------------------------
__global__ void k_prep(const float* __restrict__ W2,
                       const float* __restrict__ h_one) {
    int b = blockIdx.x;
    if (b < 16) {
        int t = b * 256 + threadIdx.x;
        int n = t >> 5;
        int k = (t & 31) * 4;
        __half2 h0 = __float22half2_rn(make_float2(W2[(k + 0) * 128 + n], W2[(k + 1) * 128 + n]));
        __half2 h1 = __float22half2_rn(make_float2(W2[(k + 2) * 128 + n], W2[(k + 3) * 128 + n]));
        u64 hp = (u64)(*(u32*)&h0) | ((u64)(*(u32*)&h1) << 32);
        *(u64*)(g_w2h + n * BSTRIDE + k * 2) = hp;
    } else {
        int bb = b - 16;
        int s = bb >> 3, ck = bb & 7;
        int c = threadIdx.x;
        const float* p = h_one + (size_t)(s * 256 + ck * 32) * 256 + c;
        float sum = 0.f;
#pragma unroll 8
        for (int r = 0; r < 32; r++) sum += p[r * 256];
        g_g1p[bb * 256 + c] = sum;
    }
}

// ---------------------------------------------------------------------------
// K2: h_one path. 128 blocks x 256 threads, 4 rows/block.
// ---------------------------------------------------------------------------
__global__ void __launch_bounds__(256)
k_one(const float* __restrict__ h_one,
      const float* __restrict__ W1,
      const float* __restrict__ b1,
      float* __restrict__ out_one) {
    __shared__ float s_in[2048];
    int tid = threadIdx.x;
    int r0 = blockIdx.x * 4;
#pragma unroll
    for (int i = 0; i < 8; i++) {
        int e = tid + i * 256;
        int k = e >> 2;
        int r = e & 3;
        int n = r0 + r;
        float v;
        if (k < 256) {
            v = h_one[n * 256 + k];
        } else {
            int sp = (k < 384) ? 0 : 1;
            int p = k - 256 - sp * 128;
            size_t base = (size_t)(sp * 2) * 65536 + (size_t)n * 128 + p;
            v = (g_g2p[base] + g_g2p[base + 65536]) * INV256;
        }
        s_in[k * 4 + r] = v;
    }
    __syncthreads();

    int c = tid;
    float acc[4] = {0.f, 0.f, 0.f, 0.f};
#pragma unroll 4
    for (int kb = 0; kb < 64; kb++) {
        float w[8];
#pragma unroll
        for (int i = 0; i < 8; i++) w[i] = W1[(kb * 8 + i) * 256 + c];
#pragma unroll
        for (int i = 0; i < 8; i++) {
            float4 a = *(const float4*)(s_in + (kb * 8 + i) * 4);
            acc[0] += a.x * w[i];
            acc[1] += a.y * w[i];
            acc[2] += a.z * w[i];
            acc[3] += a.w * w[i];
        }
    }
    float gt = b1[c];
#pragma unroll
    for (int q = 0; q < 16; q++) gt += g_gtp[q * 256 + c];
#pragma unroll
    for (int r = 0; r < 4; r++) {
        float pre = (acc[r] + gt) * RSQRT2;
        out_one[(r0 + r) * 256 + c] = (s_in[c * 4 + r] + GAIN * tanh_fast(pre)) * RSQRT2;
    }
}

// ---------------------------------------------------------------------------
// k_two helpers
// ---------------------------------------------------------------------------
__device__ __forceinline__ void mma_tile(u32 Ah, u32 Bb, float (&acc)[2][8][4]) {
#pragma unroll
    for (int mi = 0; mi < 2; mi++)
#pragma unroll
        for (int nt = 0; nt < 8; nt++)
#pragma unroll
            for (int c = 0; c < 4; c++) acc[mi][nt][c] = 0.f;
#pragma unroll
    for (int ks = 0; ks < 8; ks++) {
        u32 b[4][4], a0[4], a1[4];
#pragma unroll
        for (int nb = 0; nb < 4; nb++) ldsm4(b[nb], Bb + nb * 16 * BSTRIDE + ks * 32);
        ldsm4(a0, Ah + ks * 32);
        ldsm4(a1, Ah + 16 * BSTRIDE + ks * 32);
#pragma unroll
        for (int nb = 0; nb < 4; nb++) {
            mma16816(acc[0][nb * 2 + 0], a0, b[nb]);
            mma16816(acc[0][nb * 2 + 1], a0, b[nb] + 2);
            mma16816(acc[1][nb * 2 + 0], a1, b[nb]);
            mma16816(acc[1][nb * 2 + 1], a1, b[nb] + 2);
        }
    }
}

// stage one 128x128 tile: fp32 -> fp16 into S_AH, column sums into S_RED
__device__ __forceinline__ void stage_tile(char* smem, const float* __restrict__ src,
                                           int rr, int kc) {
    float4 csum = make_float4(0.f, 0.f, 0.f, 0.f);
#pragma unroll
    for (int it = 0; it < 16; it++) {
        int row = rr + it * 8;
        float4 v = *(const float4*)(src + (size_t)it * 8 * 65536);
        csum.x += v.x; csum.y += v.y; csum.z += v.z; csum.w += v.w;
        __half2 h0 = __float22half2_rn(make_float2(v.x, v.y));
        __half2 h1 = __float22half2_rn(make_float2(v.z, v.w));
        u64 hp = (u64)(*(u32*)&h0) | ((u64)(*(u32*)&h1) << 32);
        *(u64*)(smem + S_AH + row * BSTRIDE + kc * 8) = hp;
    }
    *(float4*)(smem + S_RED + (rr * 32 + kc) * 16) = csum;
}

__device__ __forceinline__ void epi_tile(const char* smem, float (&acc)[2][8][4],
                                         const float2* bz, size_t ibase, int j,
                                         int lane, int mw, int nw,
                                         float* __restrict__ out_two) {
    int col0 = nw * 64 + (lane & 3) * 2;
#pragma unroll
    for (int mi = 0; mi < 2; mi++) {
#pragma unroll
        for (int half = 0; half < 2; half++) {
            int rt = mw * 32 + mi * 16 + half * 8 + (lane >> 2);
            float* orow = out_two + ((ibase + rt) * 512 + j) * 128;
#pragma unroll
            for (int nt = 0; nt < 8; nt++) {
                int c = col0 + nt * 8;
                __half2 hh = *(const __half2*)(smem + S_AH + rt * BSTRIDE + c * 2);
                float2 hf = __half22float2(hh);
                float d0 = acc[mi][nt][half * 2 + 0] + bz[nt].x;
                float d1 = acc[mi][nt][half * 2 + 1] + bz[nt].y;
                float2 o;
                o.x = (hf.x + GAIN * tanh_fast(d0)) * RSQRT2;
                o.y = (hf.y + GAIN * tanh_fast(d1)) * RSQRT2;
                *(float2*)(orow + c) = o;
            }
        }
    }
}

// ---------------------------------------------------------------------------
// K3: fp16 mma.sync, j-PAIR per block with L2 prefetch. grid 1040.
// blocks < 1024: GEMM pairs; blocks 1024..1039: gt partials.
// bid -> jp = bid&255 (j0=2*jp, j1=j0+1), ch = bid>>8: s=ch>>1, h=ch&1.
// ---------------------------------------------------------------------------
__global__ void __launch_bounds__(256, 2)
k_two(const float* __restrict__ h_two,
      const float* __restrict__ b2,
      const float* __restrict__ Wg,
      float* __restrict__ out_two) {
    extern __shared__ char smem[];
    int tid = threadIdx.x;

    if (blockIdx.x >= 1024) {
        // ---- gt partials: block q covers k in [q*32, q*32+32) ----
        __shared__ float s_g1[32];
        int q = blockIdx.x - 1024;
        int c = tid;
        if (c < 32) {
            int kk = q * 32 + c;
            int s = kk >> 8;
            int col = kk & 255;
            float sum = 0.f;
#pragma unroll
            for (int ck = 0; ck < 8; ck++) sum += g_g1p[(s * 8 + ck) * 256 + col];
            s_g1[c] = sum * INV256;
        }
        __syncthreads();
        float acc = 0.f;
#pragma unroll
        for (int kb = 0; kb < 4; kb++) {
            float w[8];
#pragma unroll
            for (int i = 0; i < 8; i++) w[i] = Wg[(q * 32 + kb * 8 + i) * 256 + c];
#pragma unroll
            for (int i = 0; i < 8; i++) acc += s_g1[kb * 8 + i] * w[i];
        }
        g_gtp[q * 256 + c] = acc;
        return;
    }

    u32 sb = smem_u32(smem);
    int lane = tid & 31;
    int w = tid >> 5;

    int jp = blockIdx.x & 255;
    int ch = blockIdx.x >> 8;      // 0..3
    int s = ch >> 1;
    int h = ch & 1;
    size_t ibase = (size_t)(s * 256 + h * 128);
    int j0 = jp * 2;
    int j1 = j0 + 1;

    int rr = tid >> 5;             // 0..7
    int kc = tid & 31;             // k-quad
    const float* src0 = h_two + (ibase + rr) * 65536 + (size_t)j0 * 128 + kc * 4;
    const float* src1 = src0 + 128;

    // stage W2T fp16 image once per pair: 2176 uint4
    {
        const uint4* wh = (const uint4*)g_w2h;
        uint4* dh = (uint4*)(smem + S_WH);
        for (int idx = tid; idx < 2176; idx += 256) dh[idx] = wh[idx];
    }

    // stage tile 0, then immediately prefetch tile 1 into L2 (no registers)
    stage_tile(smem, src0, rr, kc);
#pragma unroll
    for (int it = 0; it < 16; it++) prefetch_l2(src1 + (size_t)it * 8 * 65536);
    __syncthreads();

    // g2 partial for tile 0
    if (tid < 128) {
        int p = tid;
        float sum = 0.f;
#pragma unroll
        for (int r8 = 0; r8 < 8; r8++)
            sum += *(const float*)(smem + S_RED + (r8 * 32 + (p >> 2)) * 16 + (p & 3) * 4);
        g_g2p[(size_t)(s * 2 + h) * 65536 + (size_t)j0 * 128 + p] = sum;
    }

    int mw = w & 3;       // m-block: rows mw*32
    int nw = w >> 2;      // n-block: cols nw*64

    u32 a_off = (u32)((mw * 32 + (lane & 15)) * BSTRIDE + ((lane >> 4) << 4));
    u32 b_off = (u32)((((lane & 7) + ((lane >> 4) << 3)) * BSTRIDE) + (((lane >> 3) & 1) << 4));
    u32 Ah = sb + S_AH + a_off;
    u32 Bb = sb + S_WH + (u32)(nw * 64 * BSTRIDE) + b_off;

    int col0 = nw * 64 + (lane & 3) * 2;
    float2 bz[8];
#pragma unroll
    for (int nt = 0; nt < 8; nt++) bz[nt] = *(const float2*)(b2 + col0 + nt * 8);

    float acc[2][8][4];

    // ---- tile 0 ----
    mma_tile(Ah, Bb, acc);
    epi_tile(smem, acc, bz, ibase, j0, lane, mw, nw, out_two);

    // ---- tile 1 (A loads now hit L2) ----
    __syncthreads();   // everyone done reading buf A for tile 0
    stage_tile(smem, src1, rr, kc);
    __syncthreads();

    if (tid < 128) {
        int p = tid;
        float sum = 0.f;
#pragma unroll
        for (int r8 = 0; r8 < 8; r8++)
            sum += *(const float*)(smem + S_RED + (r8 * 32 + (p >> 2)) * 16 + (p & 3) * 4);
        g_g2p[(size_t)(s * 2 + h) * 65536 + (size_t)j1 * 128 + p] = sum;
    }

    mma_tile(Ah, Bb, acc);
    epi_tile(smem, acc, bz, ibase, j1, lane, mw, nw, out_two);
}

// ---------------------------------------------------------------------------
extern "C" void kernel_launch(void* const* d_in, const int* in_sizes, int n_in,
                              void* d_out, int out_size) {
    const float* h_one = (const float*)d_in[0];
    const float* h_two = (const float*)d_in[1];
    const float* W1    = (const float*)d_in[2];
    const float* b1    = (const float*)d_in[3];
    const float* Wg    = (const float*)d_in[4];
    const float* W2    = (const float*)d_in[5];
    const float* b2    = (const float*)d_in[6];

    float* out_one = (float*)d_out;
    float* out_two = (float*)d_out + 512 * 256;

    cudaFuncSetAttribute(k_two, cudaFuncAttributeMaxDynamicSharedMemorySize, SMEM_TWO);

    k_prep<<<32, 256>>>(W2, h_one);
    k_two<<<1040, 256, SMEM_TWO>>>(h_two, b2, Wg, out_two);
    k_one<<<128, 256>>>(h_one, W1, b1, out_one);
}